// round 6
// baseline (speedup 1.0000x reference)
#include <cuda_runtime.h>
#include <cuda_bf16.h>
#include <math.h>
#include <stdint.h>

#define B_ 64
#define N_ 1024
#define C_ 256
#define K_ 512
#define T_ 64
#define NP_ 128   // T*2 pairs

// ---------------- static device scratch ----------------
static __device__ int      g_top_idx[B_][K_];
static __device__ int      g_neff[B_];
static __device__ float    g_cent[B_][K_][3];
static __device__ __align__(16) __nv_bfloat16 g_rh[B_][K_][C_];   // gathered rt hi
static __device__ __align__(16) __nv_bfloat16 g_rl[B_][K_][C_];   // gathered rt lo
static __device__ __align__(16) __nv_bfloat16 g_wh[C_][C_];       // W_in^T hi [n][k]
static __device__ __align__(16) __nv_bfloat16 g_wl[C_][C_];       // W_in^T lo
static __device__ __align__(16) __nv_bfloat16 g_fbh[B_][K_][C_];  // feat hi
static __device__ __align__(16) __nv_bfloat16 g_fbl[B_][K_][C_];  // feat lo
static __device__ float    g_fn2p[B_][K_][8];
static __device__ float    g_fn2[B_][K_];
static __device__ float    g_fn [B_][K_];
static __device__ float    g_pmv[NP_][K_][16];
static __device__ int      g_pmi[NP_][K_][16];

// ---------------- asm helpers ----------------
__device__ __forceinline__ uint32_t smem_u32(const void* p) {
    uint32_t a;
    asm("{ .reg .u64 t; cvta.to.shared.u64 t, %1; cvt.u32.u64 %0, t; }" : "=r"(a) : "l"(p));
    return a;
}
__device__ __forceinline__ void ldsm4(uint32_t* r, uint32_t a) {
    asm volatile("ldmatrix.sync.aligned.m8n8.x4.shared.b16 {%0,%1,%2,%3}, [%4];"
        : "=r"(r[0]), "=r"(r[1]), "=r"(r[2]), "=r"(r[3]) : "r"(a));
}
__device__ __forceinline__ void mma16816(float* c, const uint32_t* a, uint32_t b0, uint32_t b1) {
    asm volatile("mma.sync.aligned.m16n8k16.row.col.f32.bf16.bf16.f32 "
        "{%0,%1,%2,%3}, {%4,%5,%6,%7}, {%8,%9}, {%0,%1,%2,%3};"
        : "+f"(c[0]), "+f"(c[1]), "+f"(c[2]), "+f"(c[3])
        : "r"(a[0]), "r"(a[1]), "r"(a[2]), "r"(a[3]), "r"(b0), "r"(b1));
}
#define CP_ASYNC16(dst, src) asm volatile("cp.async.cg.shared.global [%0], [%1], 16;" :: "r"(dst), "l"(src))
#define CP_COMMIT()          asm volatile("cp.async.commit_group;" ::: "memory")
#define CP_WAIT0()           asm volatile("cp.async.wait_group 0;" ::: "memory")

__device__ __forceinline__ uint32_t split_pack_hi(float v0, float v1, uint32_t& lo) {
    __nv_bfloat16 h0 = __float2bfloat16_rn(v0);
    __nv_bfloat16 h1 = __float2bfloat16_rn(v1);
    __nv_bfloat16 l0 = __float2bfloat16_rn(v0 - __bfloat162float(h0));
    __nv_bfloat16 l1 = __float2bfloat16_rn(v1 - __bfloat162float(h1));
    lo = (uint32_t)__bfloat16_as_ushort(l0) | ((uint32_t)__bfloat16_as_ushort(l1) << 16);
    return (uint32_t)__bfloat16_as_ushort(h0) | ((uint32_t)__bfloat16_as_ushort(h1) << 16);
}

// ---------------- kernel 1: masked top-K via bitonic sort ----------------
__global__ void k_topk(const float* __restrict__ attn,
                       const int*   __restrict__ num_rt,
                       const float* __restrict__ cents,
                       const float* __restrict__ sas) {
    int b = blockIdx.x;
    __shared__ float sv[N_];
    __shared__ int   si[N_];
    int nr = num_rt[b];
    for (int i = threadIdx.x; i < N_; i += blockDim.x) {
        sv[i] = (i < nr) ? attn[b * N_ + i] : -1e9f;
        si[i] = i;
    }
    for (int size = 2; size <= N_; size <<= 1) {
        for (int stride = size >> 1; stride > 0; stride >>= 1) {
            __syncthreads();
            for (int i = threadIdx.x; i < N_; i += blockDim.x) {
                int j = i ^ stride;
                if (j > i) {
                    float vi = sv[i], vj = sv[j];
                    int   ii = si[i], ij = si[j];
                    bool up = ((i & size) == 0);
                    bool jFirst = (vj > vi) || (vj == vi && ij < ii);
                    bool iFirst = (vi > vj) || (vi == vj && ii < ij);
                    bool sw = up ? jFirst : iFirst;
                    if (sw) { sv[i] = vj; sv[j] = vi; si[i] = ij; si[j] = ii; }
                }
            }
        }
    }
    __syncthreads();
    float sh0 = sas[b*4+0], sh1 = sas[b*4+1], sh2 = sas[b*4+2], sc = sas[b*4+3];
    for (int k = threadIdx.x; k < K_; k += blockDim.x) {
        int id = si[k];
        g_top_idx[b][k] = id;
        const float* cp = cents + ((size_t)b * N_ + id) * 3;
        float x = cp[0], y = cp[1], z = cp[2];
        if (id < nr) { x = fmaf(x, sc, sh0); y = fmaf(y, sc, sh1); z = fmaf(z, sc, sh2); }
        g_cent[b][k][0] = x; g_cent[b][k][1] = y; g_cent[b][k][2] = z;
    }
    if (threadIdx.x == 0) g_neff[b] = nr < K_ ? nr : K_;
}

// ---------------- prep: W_in^T bf16 hi/lo ----------------
__global__ void k_wt(const float* __restrict__ W_in) {
    int k = blockIdx.x, n = threadIdx.x;
    float v = W_in[k * C_ + n];
    __nv_bfloat16 h = __float2bfloat16_rn(v);
    __nv_bfloat16 l = __float2bfloat16_rn(v - __bfloat162float(h));
    g_wh[n][k] = h;
    g_wl[n][k] = l;
}

// ---------------- prep: gather top-K rt rows to bf16 hi/lo ----------------
__global__ void k_gather(const float* __restrict__ rt) {
    int idx  = blockIdx.x * 8 + (threadIdx.x >> 5);
    int lane = threadIdx.x & 31;
    int b = idx >> 9, k = idx & (K_ - 1);
    int src = g_top_idx[b][k];
    const float4* r = (const float4*)(rt + ((size_t)b * N_ + src) * C_);
    float4 u = r[lane * 2], w2 = r[lane * 2 + 1];
    float f[8] = {u.x, u.y, u.z, u.w, w2.x, w2.y, w2.z, w2.w};
    uint32_t hw[4], lw[4];
#pragma unroll
    for (int q = 0; q < 4; q++) hw[q] = split_pack_hi(f[q*2], f[q*2+1], lw[q]);
    *(uint4*)&g_rh[b][k][lane * 8] = make_uint4(hw[0], hw[1], hw[2], hw[3]);
    *(uint4*)&g_rl[b][k][lane * 8] = make_uint4(lw[0], lw[1], lw[2], lw[3]);
}

// ---------------- shared GEMM plumbing (128x128 tile, K-chunk 64, 2 stages, 512 thr) ----------------
__device__ __forceinline__ void gem_prefetch(const uint4* const* gsrc, uint32_t sb,
                                             int tid, int kc, int stage) {
    uint32_t dbase = sb + stage * 65536;
#pragma unroll
    for (int tl = 0; tl < 4; tl++) {
        const uint4* s = gsrc[tl];
#pragma unroll
        for (int i = 0; i < 2; i++) {
            int idx = tid + i * 512;
            int rr = idx >> 3, uu = idx & 7;
            uint32_t d = dbase + tl * 16384 + (((rr << 3) + (uu ^ (rr & 7))) << 4);
            CP_ASYNC16(d, s + rr * 32 + kc * 8 + uu);
        }
    }
    CP_COMMIT();
}

// mainloop: 3-term bf16 MMA; 16 warps, each owns 32x32 output; acc[2][4][4]
__device__ __forceinline__ void gem_mainloop(const uint4* const* gsrc, uint32_t sb,
                                             int tid, float acc[2][4][4]) {
    int lane = tid & 31, wid = tid >> 5;
    int wr = wid >> 2, wc = wid & 3;
    int mat = lane >> 3, rlo = lane & 7;
    gem_prefetch(gsrc, sb, tid, 0, 0);
    for (int kc = 0; kc < 4; kc++) {
        CP_WAIT0();
        __syncthreads();
        if (kc < 3) gem_prefetch(gsrc, sb, tid, kc + 1, (kc + 1) & 1);
        uint32_t tb = sb + (kc & 1) * 65536;
#pragma unroll
        for (int ks = 0; ks < 4; ks++) {
            int ku = 2 * ks + (mat >> 1);
            uint32_t af[2][2][4];
#pragma unroll
            for (int mb = 0; mb < 2; mb++) {
                int row = wr * 32 + mb * 16 + rlo + ((mat & 1) << 3);
                uint32_t ad = (((row << 3) + (ku ^ (row & 7))) << 4);
                ldsm4(af[mb][0], tb + ad);
                ldsm4(af[mb][1], tb + 16384 + ad);
            }
#pragma unroll
            for (int nbp = 0; nbp < 2; nbp++) {
                int rowb = wc * 32 + nbp * 16 + rlo + ((mat & 1) << 3);
                uint32_t ab = (((rowb << 3) + (ku ^ (rowb & 7))) << 4);
                uint32_t bh[4], bl[4];
                ldsm4(bh, tb + 32768 + ab);
                ldsm4(bl, tb + 49152 + ab);
#pragma unroll
                for (int mb = 0; mb < 2; mb++) {
                    mma16816(acc[mb][nbp*2],   af[mb][0], bh[0], bh[2]);
                    mma16816(acc[mb][nbp*2],   af[mb][0], bl[0], bl[2]);
                    mma16816(acc[mb][nbp*2],   af[mb][1], bh[0], bh[2]);
                    mma16816(acc[mb][nbp*2+1], af[mb][0], bh[1], bh[3]);
                    mma16816(acc[mb][nbp*2+1], af[mb][0], bl[1], bl[3]);
                    mma16816(acc[mb][nbp*2+1], af[mb][1], bh[1], bh[3]);
                }
            }
        }
        __syncthreads();
    }
}

// ---------------- kernel 2: feat = gather(rt) @ W_in + b_in via MMA ----------------
__global__ void __launch_bounds__(512)
k_featmma(const float* __restrict__ b_in) {
    extern __shared__ __align__(128) unsigned char dsm[];
    int b     = blockIdx.z;
    int rtile = blockIdx.y;
    int ctile = blockIdx.x;          // n half: 0 or 1
    int tid = threadIdx.x, lane = tid & 31, wid = tid >> 5;
    int wr = wid >> 2, wc = wid & 3;
    uint32_t sb = smem_u32(dsm);

    const uint4* gsrc[4];
    gsrc[0] = (const uint4*)&g_rh[b][rtile * 128][0];
    gsrc[1] = (const uint4*)&g_rl[b][rtile * 128][0];
    gsrc[2] = (const uint4*)&g_wh[ctile * 128][0];
    gsrc[3] = (const uint4*)&g_wl[ctile * 128][0];

    float acc[2][4][4];
#pragma unroll
    for (int mb = 0; mb < 2; mb++)
#pragma unroll
        for (int nb = 0; nb < 4; nb++)
#pragma unroll
            for (int c = 0; c < 4; c++) acc[mb][nb][c] = 0.f;

    gem_mainloop(gsrc, sb, tid, acc);

    int t4 = lane >> 2, q = lane & 3;
#pragma unroll
    for (int mb = 0; mb < 2; mb++) {
#pragma unroll
        for (int half = 0; half < 2; half++) {
            int row = rtile * 128 + wr * 32 + mb * 16 + t4 + half * 8;
            float s8 = 0.f;
#pragma unroll
            for (int nb = 0; nb < 4; nb++) {
                int col = ctile * 128 + wc * 32 + nb * 8 + q * 2;
                float f0 = acc[mb][nb][half*2+0] + b_in[col];
                float f1 = acc[mb][nb][half*2+1] + b_in[col + 1];
                uint32_t lw;
                uint32_t hw = split_pack_hi(f0, f1, lw);
                *(uint32_t*)&g_fbh[b][row][col] = hw;
                *(uint32_t*)&g_fbl[b][row][col] = lw;
                s8 += f0 * f0 + f1 * f1;
            }
            s8 += __shfl_xor_sync(0xffffffffu, s8, 1);
            s8 += __shfl_xor_sync(0xffffffffu, s8, 2);
            if (q == 0) g_fn2p[b][row][ctile * 4 + wc] = s8;
        }
    }
}

// ---------------- kernel 2b: finalize norms ----------------
__global__ void k_fn() {
    int i = blockIdx.x * 256 + threadIdx.x;
    const float* pp = &g_fn2p[0][0][0] + (size_t)i * 8;
    float s = ((pp[0] + pp[1]) + (pp[2] + pp[3])) + ((pp[4] + pp[5]) + (pp[6] + pp[7]));
    (&g_fn2[0][0])[i] = s;
    (&g_fn [0][0])[i] = sqrtf(s);
}

// ---------------- kernel 3: G tile + fused partial argmin ----------------
__global__ void __launch_bounds__(512)
k_gemm(const int* __restrict__ anc,
       const int* __restrict__ pos,
       const int* __restrict__ neg) {
    extern __shared__ __align__(128) unsigned char dsm[];
    int p = blockIdx.z;
    int t = p >> 1, nn = p & 1;
    int ba = anc[t];
    int bb = nn ? neg[t] : pos[t];
    int rtile = blockIdx.y, ctile = blockIdx.x;
    int tid = threadIdx.x, lane = tid & 31, wid = tid >> 5;
    int wr = wid >> 2, wc = wid & 3;
    uint32_t sb = smem_u32(dsm);

    const uint4* gsrc[4];
    gsrc[0] = (const uint4*)&g_fbh[ba][rtile * 128][0];
    gsrc[1] = (const uint4*)&g_fbl[ba][rtile * 128][0];
    gsrc[2] = (const uint4*)&g_fbh[bb][ctile * 128][0];
    gsrc[3] = (const uint4*)&g_fbl[bb][ctile * 128][0];

    float acc[2][4][4];
#pragma unroll
    for (int mb = 0; mb < 2; mb++)
#pragma unroll
        for (int nb = 0; nb < 4; nb++)
#pragma unroll
            for (int c = 0; c < 4; c++) acc[mb][nb][c] = 0.f;

    gem_mainloop(gsrc, sb, tid, acc);

    int t4 = lane >> 2, q = lane & 3;
    float fnc[8];
#pragma unroll
    for (int nb = 0; nb < 4; nb++)
#pragma unroll
        for (int e = 0; e < 2; e++)
            fnc[nb*2+e] = g_fn2[bb][ctile*128 + wc*32 + nb*8 + q*2 + e];
#pragma unroll
    for (int mb = 0; mb < 2; mb++) {
#pragma unroll
        for (int half = 0; half < 2; half++) {
            int row = rtile*128 + wr*32 + mb*16 + t4 + half*8;
            float bv = 3.4e38f; int bi = 0x7fffffff;
#pragma unroll
            for (int nb = 0; nb < 4; nb++) {
#pragma unroll
                for (int e = 0; e < 2; e++) {
                    float fd = fnc[nb*2+e] - 2.f * acc[mb][nb][half*2+e];
                    int col = ctile*128 + wc*32 + nb*8 + q*2 + e;
                    if (fd < bv) { bv = fd; bi = col; }
                }
            }
#pragma unroll
            for (int off = 1; off < 4; off <<= 1) {
                float ov = __shfl_xor_sync(0xffffffffu, bv, off);
                int   oi = __shfl_xor_sync(0xffffffffu, bi, off);
                if (ov < bv || (ov == bv && oi < bi)) { bv = ov; bi = oi; }
            }
            if (q == 0) {
                g_pmv[p][row][ctile*4 + wc] = bv;
                g_pmi[p][row][ctile*4 + wc] = bi;
            }
        }
    }
}

// ---------------- kernel 4: fused tail (corr reduce + mask + power + MLP) ----------------
__global__ void __launch_bounds__(512)
k_tail(const int* __restrict__ anc, const int* __restrict__ pos,
       const int* __restrict__ neg,
       const float* __restrict__ W1, const float* __restrict__ b1,
       const float* __restrict__ W2, const float* __restrict__ b2,
       float* __restrict__ out) {
    extern __shared__ __align__(16) unsigned char dsm[];
    unsigned (*msk)[16] = (unsigned(*)[16])dsm;              // 32 KB
    float* px   = (float*)(dsm + 32768);
    float* py   = px + K_;
    float* pz   = py + K_;
    float* pn   = pz + K_;
    float* qx   = pn + K_;
    float* qy   = qx + K_;
    float* qz   = qy + K_;
    float* qn   = qz + K_;
    float* s_sm = qn + K_;
    float* v    = s_sm + K_;
    float* w    = v + K_;
    float* u    = w + K_;
    float* red  = u + K_;

    int p = blockIdx.x;
    int tid = threadIdx.x;
    int warp = tid >> 5, lane = tid & 31;
    int t = p >> 1, n = p & 1;
    int ba = anc[t];
    int bb = n ? neg[t] : pos[t];

    // ---- stage 1: reduce argmin partials -> s, q_c ----
    {
        int k = tid;
        float bv = 3.4e38f; int bi = 0x7fffffff;
#pragma unroll
        for (int j = 0; j < 16; j++) {
            float pv = g_pmv[p][k][j];
            int   pi = g_pmi[p][k][j];
            if (pv < bv || (pv == bv && pi < bi)) { bv = pv; bi = pi; }
        }
        float fn2b = g_fn2[bb][bi];
        float dot  = 0.5f * (fn2b - bv);
        float cosv = dot / (g_fn[ba][k] * g_fn[bb][bi] + 1e-8f);
        s_sm[k] = cosv > 0.f ? cosv : 0.f;
        float x = g_cent[ba][k][0], y = g_cent[ba][k][1], z = g_cent[ba][k][2];
        px[k] = x; py[k] = y; pz[k] = z; pn[k] = x*x + y*y + z*z;
        x = g_cent[bb][bi][0]; y = g_cent[bb][bi][1]; z = g_cent[bb][bi][2];
        qx[k] = x; qy[k] = y; qz[k] = z; qn[k] = x*x + y*y + z*z;
    }
    __syncthreads();

    // ---- stage 2: geo mask via ballot, into SMEM ----
    {
        int neffa = g_neff[ba], neffb = g_neff[bb];
        for (int k = warp; k < K_; k += 16) {
            float pxk = px[k], pyk = py[k], pzk = pz[k], pnk = pn[k];
            float qxk = qx[k], qyk = qy[k], qzk = qz[k], qnk = qn[k];
            bool kv = (k < neffa);
#pragma unroll 4
            for (int ww = 0; ww < 16; ww++) {
                int l = ww * 32 + lane;
                float dp2 = fmaxf(pnk + pn[l] - 2.f*(pxk*px[l] + pyk*py[l] + pzk*pz[l]), 0.f) + 1e-12f;
                float dq2 = fmaxf(qnk + qn[l] - 2.f*(qxk*qx[l] + qyk*qy[l] + qzk*qz[l]), 0.f) + 1e-12f;
                float uu = dp2 + dq2 - 0.25f;
                bool geo = (uu < 0.f) || (4.f * dp2 * dq2 > uu * uu);
                bool ok = geo && kv && (l < neffb) && (l != k);
                unsigned word = __ballot_sync(0xffffffffu, ok);
                if (lane == 0) msk[k][ww] = word;
            }
        }
    }
    v[tid] = 0.044194173824159216f;   // 1/sqrt(512)
    __syncthreads();

    // ---- stage 3: power iteration ----
    for (int it = 0; it < 20; it++) {
        u[tid] = s_sm[tid] * v[tid];
        __syncthreads();
        float ur[16];
#pragma unroll
        for (int c = 0; c < 16; c++) ur[c] = u[c * 32 + lane];
        for (int k = warp; k < K_; k += 16) {
            const uint4* m4 = (const uint4*)msk[k];
            float acc = 0.f;
#pragma unroll
            for (int c4 = 0; c4 < 4; c4++) {
                uint4 mw = m4[c4];
                if ((mw.x >> lane) & 1u) acc += ur[c4 * 4 + 0];
                if ((mw.y >> lane) & 1u) acc += ur[c4 * 4 + 1];
                if ((mw.z >> lane) & 1u) acc += ur[c4 * 4 + 2];
                if ((mw.w >> lane) & 1u) acc += ur[c4 * 4 + 3];
            }
#pragma unroll
            for (int o = 16; o; o >>= 1) acc += __shfl_xor_sync(0xffffffffu, acc, o);
            if (lane == 0) w[k] = acc * s_sm[k];
        }
        __syncthreads();
        float x = w[tid];
        float sq = x * x;
#pragma unroll
        for (int o = 16; o; o >>= 1) sq += __shfl_xor_sync(0xffffffffu, sq, o);
        if (lane == 0) red[warp] = sq;
        __syncthreads();
        if (warp == 0) {
            float r = (lane < 16) ? red[lane] : 0.f;
#pragma unroll
            for (int o = 8; o; o >>= 1) r += __shfl_xor_sync(0xffffffffu, r, o);
            if (lane == 0) red[0] = 1.f / (sqrtf(r) + 1e-8f);
        }
        __syncthreads();
        v[tid] = x * red[0];
        __syncthreads();
    }
    // ---- sort descending ----
    for (int size = 2; size <= K_; size <<= 1) {
        for (int stride = size >> 1; stride > 0; stride >>= 1) {
            int i = tid, j = i ^ stride;
            if (j > i) {
                float vi = v[i], vj = v[j];
                bool up = ((i & size) == 0);
                bool sw = up ? (vj > vi) : (vi > vj);
                if (sw) { v[i] = vj; v[j] = vi; }
            }
            __syncthreads();
        }
    }
    // ---- MLP ----
    float hj = b1[tid];
#pragma unroll 4
    for (int k = 0; k < K_; k++)
        hj = fmaf(v[k], W1[(size_t)k * K_ + tid], hj);
    hj = hj > 0.f ? hj : 0.f;
    float contrib = hj * W2[tid];
#pragma unroll
    for (int o = 16; o; o >>= 1) contrib += __shfl_xor_sync(0xffffffffu, contrib, o);
    if (lane == 0) red[warp] = contrib;
    __syncthreads();
    if (tid == 0) {
        float sum = 0.f;
#pragma unroll
        for (int i = 0; i < 16; i++) sum += red[i];
        sum += b2[0];
        out[p]       = 1.f / (1.f + expf(-sum));
        out[NP_ + p] = (p & 1) ? 0.f : 1.f;
    }
}

extern "C" void kernel_launch(void* const* d_in, const int* in_sizes, int n_in,
                              void* d_out, int out_size) {
    const float* rt     = (const float*)d_in[0];
    const float* cents  = (const float*)d_in[1];
    const float* attn   = (const float*)d_in[2];
    const float* sas    = (const float*)d_in[3];
    const int*   num_rt = (const int*)  d_in[4];
    const int*   anc    = (const int*)  d_in[5];
    const int*   pos    = (const int*)  d_in[6];
    const int*   neg    = (const int*)  d_in[7];
    const float* W_in   = (const float*)d_in[8];
    const float* b_in   = (const float*)d_in[9];
    const float* W1     = (const float*)d_in[10];
    const float* b1     = (const float*)d_in[11];
    const float* W2     = (const float*)d_in[12];
    const float* b2     = (const float*)d_in[13];
    float* out = (float*)d_out;

    static int s_init = 0;
    if (!s_init) {
        cudaFuncSetAttribute(k_featmma, cudaFuncAttributeMaxDynamicSharedMemorySize, 131072);
        cudaFuncSetAttribute(k_gemm,    cudaFuncAttributeMaxDynamicSharedMemorySize, 131072);
        cudaFuncSetAttribute(k_tail,    cudaFuncAttributeMaxDynamicSharedMemorySize, 57472);
        s_init = 1;
    }

    k_topk   <<<B_, 512>>>(attn, num_rt, cents, sas);
    k_wt     <<<C_, C_>>>(W_in);
    k_gather <<<B_*K_/8, 256>>>(rt);
    k_featmma<<<dim3(2, 4, B_), 512, 131072>>>(b_in);
    k_fn     <<<B_*K_/256, 256>>>();
    k_gemm   <<<dim3(4, 4, NP_), 512, 131072>>>(anc, pos, neg);
    k_tail   <<<NP_, 512, 57472>>>(anc, pos, neg, W1, b1, W2, b2, out);
}

// round 7
// speedup vs baseline: 1.0508x; 1.0508x over previous
#include <cuda_runtime.h>
#include <cuda_bf16.h>
#include <math.h>
#include <stdint.h>

#define B_ 64
#define N_ 1024
#define C_ 256
#define K_ 512
#define T_ 64
#define NP_ 128   // T*2 pairs

// ---------------- static device scratch ----------------
static __device__ int      g_top_idx[B_][K_];
static __device__ int      g_neff[B_];
static __device__ float    g_cent[B_][K_][3];
static __device__ __align__(16) __nv_bfloat16 g_rh[B_][K_][C_];   // gathered rt hi
static __device__ __align__(16) __nv_bfloat16 g_rl[B_][K_][C_];   // gathered rt lo
static __device__ __align__(16) __nv_bfloat16 g_wh[C_][C_];       // W_in^T hi [n][k]
static __device__ __align__(16) __nv_bfloat16 g_wl[C_][C_];       // W_in^T lo
static __device__ __align__(16) __nv_bfloat16 g_fbh[B_][K_][C_];  // feat hi
static __device__ __align__(16) __nv_bfloat16 g_fbl[B_][K_][C_];  // feat lo
static __device__ float    g_fn2p[B_][K_][4];
static __device__ float    g_fn2[B_][K_];
static __device__ float    g_fn [B_][K_];
static __device__ float    g_pmv[NP_][K_][8];
static __device__ int      g_pmi[NP_][K_][8];

// ---------------- asm helpers ----------------
__device__ __forceinline__ uint32_t smem_u32(const void* p) {
    uint32_t a;
    asm("{ .reg .u64 t; cvta.to.shared.u64 t, %1; cvt.u32.u64 %0, t; }" : "=r"(a) : "l"(p));
    return a;
}
__device__ __forceinline__ void ldsm4(uint32_t* r, uint32_t a) {
    asm volatile("ldmatrix.sync.aligned.m8n8.x4.shared.b16 {%0,%1,%2,%3}, [%4];"
        : "=r"(r[0]), "=r"(r[1]), "=r"(r[2]), "=r"(r[3]) : "r"(a));
}
__device__ __forceinline__ void mma16816(float* c, const uint32_t* a, uint32_t b0, uint32_t b1) {
    asm volatile("mma.sync.aligned.m16n8k16.row.col.f32.bf16.bf16.f32 "
        "{%0,%1,%2,%3}, {%4,%5,%6,%7}, {%8,%9}, {%0,%1,%2,%3};"
        : "+f"(c[0]), "+f"(c[1]), "+f"(c[2]), "+f"(c[3])
        : "r"(a[0]), "r"(a[1]), "r"(a[2]), "r"(a[3]), "r"(b0), "r"(b1));
}
#define CP_ASYNC16(dst, src) asm volatile("cp.async.cg.shared.global [%0], [%1], 16;" :: "r"(dst), "l"(src))
#define CP_COMMIT()          asm volatile("cp.async.commit_group;" ::: "memory")
#define CP_WAIT0()           asm volatile("cp.async.wait_group 0;" ::: "memory")
#define CP_WAIT1()           asm volatile("cp.async.wait_group 1;" ::: "memory")

// SW64 swizzle for 64B-wide rows (conflict-free 8-row ldmatrix)
#define SWZ64(off) ((off) ^ (((off) >> 3) & 0x30))

__device__ __forceinline__ uint32_t split_pack_hi(float v0, float v1, uint32_t& lo) {
    __nv_bfloat16 h0 = __float2bfloat16_rn(v0);
    __nv_bfloat16 h1 = __float2bfloat16_rn(v1);
    __nv_bfloat16 l0 = __float2bfloat16_rn(v0 - __bfloat162float(h0));
    __nv_bfloat16 l1 = __float2bfloat16_rn(v1 - __bfloat162float(h1));
    lo = (uint32_t)__bfloat16_as_ushort(l0) | ((uint32_t)__bfloat16_as_ushort(l1) << 16);
    return (uint32_t)__bfloat16_as_ushort(h0) | ((uint32_t)__bfloat16_as_ushort(h1) << 16);
}

// ---------------- kernel 1: masked top-K via bitonic sort ----------------
__global__ void k_topk(const float* __restrict__ attn,
                       const int*   __restrict__ num_rt,
                       const float* __restrict__ cents,
                       const float* __restrict__ sas) {
    int b = blockIdx.x;
    __shared__ float sv[N_];
    __shared__ int   si[N_];
    int nr = num_rt[b];
    for (int i = threadIdx.x; i < N_; i += blockDim.x) {
        sv[i] = (i < nr) ? attn[b * N_ + i] : -1e9f;
        si[i] = i;
    }
    for (int size = 2; size <= N_; size <<= 1) {
        for (int stride = size >> 1; stride > 0; stride >>= 1) {
            __syncthreads();
            for (int i = threadIdx.x; i < N_; i += blockDim.x) {
                int j = i ^ stride;
                if (j > i) {
                    float vi = sv[i], vj = sv[j];
                    int   ii = si[i], ij = si[j];
                    bool up = ((i & size) == 0);
                    bool jFirst = (vj > vi) || (vj == vi && ij < ii);
                    bool iFirst = (vi > vj) || (vi == vj && ii < ij);
                    bool sw = up ? jFirst : iFirst;
                    if (sw) { sv[i] = vj; sv[j] = vi; si[i] = ij; si[j] = ii; }
                }
            }
        }
    }
    __syncthreads();
    float sh0 = sas[b*4+0], sh1 = sas[b*4+1], sh2 = sas[b*4+2], sc = sas[b*4+3];
    for (int k = threadIdx.x; k < K_; k += blockDim.x) {
        int id = si[k];
        g_top_idx[b][k] = id;
        const float* cp = cents + ((size_t)b * N_ + id) * 3;
        float x = cp[0], y = cp[1], z = cp[2];
        if (id < nr) { x = fmaf(x, sc, sh0); y = fmaf(y, sc, sh1); z = fmaf(z, sc, sh2); }
        g_cent[b][k][0] = x; g_cent[b][k][1] = y; g_cent[b][k][2] = z;
    }
    if (threadIdx.x == 0) g_neff[b] = nr < K_ ? nr : K_;
}

// ---------------- prep: W_in^T bf16 hi/lo ----------------
__global__ void k_wt(const float* __restrict__ W_in) {
    int k = blockIdx.x, n = threadIdx.x;
    float v = W_in[k * C_ + n];
    __nv_bfloat16 h = __float2bfloat16_rn(v);
    __nv_bfloat16 l = __float2bfloat16_rn(v - __bfloat162float(h));
    g_wh[n][k] = h;
    g_wl[n][k] = l;
}

// ---------------- prep: gather top-K rt rows to bf16 hi/lo ----------------
__global__ void k_gather(const float* __restrict__ rt) {
    int idx  = blockIdx.x * 8 + (threadIdx.x >> 5);
    int lane = threadIdx.x & 31;
    int b = idx >> 9, k = idx & (K_ - 1);
    int src = g_top_idx[b][k];
    const float4* r = (const float4*)(rt + ((size_t)b * N_ + src) * C_);
    float4 u = r[lane * 2], w2 = r[lane * 2 + 1];
    float f[8] = {u.x, u.y, u.z, u.w, w2.x, w2.y, w2.z, w2.w};
    uint32_t hw[4], lw[4];
#pragma unroll
    for (int q = 0; q < 4; q++) hw[q] = split_pack_hi(f[q*2], f[q*2+1], lw[q]);
    *(uint4*)&g_rh[b][k][lane * 8] = make_uint4(hw[0], hw[1], hw[2], hw[3]);
    *(uint4*)&g_rl[b][k][lane * 8] = make_uint4(lw[0], lw[1], lw[2], lw[3]);
}

// ---------------- GEMM plumbing: 128x128 tile, K-chunk 32 (SW64), 3 stages ----------------
// Stage = 4 tiles (Ah,Al,Bh,Bl) x 128 rows x 64B = 32 KB. 3 stages = 96 KB -> 2 CTAs/SM.
__device__ __forceinline__ void gem_prefetch(const uint4* const* gsrc, uint32_t sb,
                                             int tid, int kc, int stage) {
    uint32_t dbase = sb + stage * 32768;
#pragma unroll
    for (int tl = 0; tl < 4; tl++) {
        const uint4* s = gsrc[tl];
#pragma unroll
        for (int i = 0; i < 2; i++) {
            int idx = tid + i * 256;
            int rr = idx >> 2, uu = idx & 3;
            uint32_t off = (uint32_t)((rr << 6) + (uu << 4));
            CP_ASYNC16(dbase + tl * 8192 + SWZ64(off), s + rr * 32 + kc * 4 + uu);
        }
    }
    CP_COMMIT();
}

// mainloop: 8 K-chunks of 32; 8 warps, each owns 64x64 output; acc[2][8][4]
__device__ __forceinline__ void gem_mainloop(const uint4* const* gsrc, uint32_t sb,
                                             int tid, float acc[2][8][4]) {
    int lane = tid & 31, wid = tid >> 5;
    int wr = wid >> 1, wc = wid & 1;
    int mat = lane >> 3, rlo = lane & 7;
    gem_prefetch(gsrc, sb, tid, 0, 0);
    gem_prefetch(gsrc, sb, tid, 1, 1);
    for (int kc = 0; kc < 8; kc++) {
        if (kc < 7) { CP_WAIT1(); } else { CP_WAIT0(); }
        __syncthreads();
        if (kc < 6) {
            int nkc = kc + 2;
            gem_prefetch(gsrc, sb, tid, nkc, nkc - (nkc / 3) * 3);
        }
        uint32_t tb = sb + (kc - (kc / 3) * 3) * 32768;
#pragma unroll
        for (int ks = 0; ks < 2; ks++) {
            int ku = 2 * ks + (mat >> 1);
            uint32_t af[2][2][4];
#pragma unroll
            for (int mb = 0; mb < 2; mb++) {
                int row = wr * 32 + mb * 16 + rlo + ((mat & 1) << 3);
                uint32_t off = (uint32_t)(row * 64 + ku * 16);
                uint32_t ad = SWZ64(off);
                ldsm4(af[mb][0], tb + ad);
                ldsm4(af[mb][1], tb + 8192 + ad);
            }
#pragma unroll
            for (int nbp = 0; nbp < 4; nbp++) {
                int rowb = wc * 64 + nbp * 16 + rlo + ((mat & 1) << 3);
                uint32_t offb = (uint32_t)(rowb * 64 + ku * 16);
                uint32_t ab = SWZ64(offb);
                uint32_t bh[4], bl[4];
                ldsm4(bh, tb + 16384 + ab);
                ldsm4(bl, tb + 24576 + ab);
#pragma unroll
                for (int mb = 0; mb < 2; mb++) {
                    mma16816(acc[mb][nbp*2],   af[mb][0], bh[0], bh[2]);
                    mma16816(acc[mb][nbp*2],   af[mb][0], bl[0], bl[2]);
                    mma16816(acc[mb][nbp*2],   af[mb][1], bh[0], bh[2]);
                    mma16816(acc[mb][nbp*2+1], af[mb][0], bh[1], bh[3]);
                    mma16816(acc[mb][nbp*2+1], af[mb][0], bl[1], bl[3]);
                    mma16816(acc[mb][nbp*2+1], af[mb][1], bh[1], bh[3]);
                }
            }
        }
    }
    __syncthreads();
}

// ---------------- kernel 2: feat = gather(rt) @ W_in + b_in via MMA ----------------
__global__ void __launch_bounds__(256, 2)
k_featmma(const float* __restrict__ b_in) {
    extern __shared__ __align__(128) unsigned char dsm[];
    int b     = blockIdx.z;
    int rtile = blockIdx.y;
    int ctile = blockIdx.x;          // n half: 0 or 1
    int tid = threadIdx.x, lane = tid & 31, wid = tid >> 5;
    int wr = wid >> 1, wc = wid & 1;
    uint32_t sb = smem_u32(dsm);

    const uint4* gsrc[4];
    gsrc[0] = (const uint4*)&g_rh[b][rtile * 128][0];
    gsrc[1] = (const uint4*)&g_rl[b][rtile * 128][0];
    gsrc[2] = (const uint4*)&g_wh[ctile * 128][0];
    gsrc[3] = (const uint4*)&g_wl[ctile * 128][0];

    float acc[2][8][4];
#pragma unroll
    for (int mb = 0; mb < 2; mb++)
#pragma unroll
        for (int nb = 0; nb < 8; nb++)
#pragma unroll
            for (int c = 0; c < 4; c++) acc[mb][nb][c] = 0.f;

    gem_mainloop(gsrc, sb, tid, acc);

    int t4 = lane >> 2, q = lane & 3;
#pragma unroll
    for (int mb = 0; mb < 2; mb++) {
#pragma unroll
        for (int half = 0; half < 2; half++) {
            int row = rtile * 128 + wr * 32 + mb * 16 + t4 + half * 8;
            float s8 = 0.f;
#pragma unroll
            for (int nb = 0; nb < 8; nb++) {
                int col = ctile * 128 + wc * 64 + nb * 8 + q * 2;
                float f0 = acc[mb][nb][half*2+0] + b_in[col];
                float f1 = acc[mb][nb][half*2+1] + b_in[col + 1];
                uint32_t lw;
                uint32_t hw = split_pack_hi(f0, f1, lw);
                *(uint32_t*)&g_fbh[b][row][col] = hw;
                *(uint32_t*)&g_fbl[b][row][col] = lw;
                s8 += f0 * f0 + f1 * f1;
            }
            s8 += __shfl_xor_sync(0xffffffffu, s8, 1);
            s8 += __shfl_xor_sync(0xffffffffu, s8, 2);
            if (q == 0) g_fn2p[b][row][ctile * 2 + wc] = s8;
        }
    }
}

// ---------------- kernel 2b: finalize norms ----------------
__global__ void k_fn() {
    int i = blockIdx.x * 256 + threadIdx.x;
    const float* pp = &g_fn2p[0][0][0] + (size_t)i * 4;
    float s = (pp[0] + pp[1]) + (pp[2] + pp[3]);
    (&g_fn2[0][0])[i] = s;
    (&g_fn [0][0])[i] = sqrtf(s);
}

// ---------------- kernel 3: G tile + fused partial argmin ----------------
__global__ void __launch_bounds__(256, 2)
k_gemm(const int* __restrict__ anc,
       const int* __restrict__ pos,
       const int* __restrict__ neg) {
    extern __shared__ __align__(128) unsigned char dsm[];
    int p = blockIdx.z;
    int t = p >> 1, nn = p & 1;
    int ba = anc[t];
    int bb = nn ? neg[t] : pos[t];
    int rtile = blockIdx.y, ctile = blockIdx.x;
    int tid = threadIdx.x, lane = tid & 31, wid = tid >> 5;
    int wr = wid >> 1, wc = wid & 1;
    uint32_t sb = smem_u32(dsm);

    const uint4* gsrc[4];
    gsrc[0] = (const uint4*)&g_fbh[ba][rtile * 128][0];
    gsrc[1] = (const uint4*)&g_fbl[ba][rtile * 128][0];
    gsrc[2] = (const uint4*)&g_fbh[bb][ctile * 128][0];
    gsrc[3] = (const uint4*)&g_fbl[bb][ctile * 128][0];

    float acc[2][8][4];
#pragma unroll
    for (int mb = 0; mb < 2; mb++)
#pragma unroll
        for (int nb = 0; nb < 8; nb++)
#pragma unroll
            for (int c = 0; c < 4; c++) acc[mb][nb][c] = 0.f;

    gem_mainloop(gsrc, sb, tid, acc);

    int t4 = lane >> 2, q = lane & 3;
    float fnc[16];
#pragma unroll
    for (int nb = 0; nb < 8; nb++)
#pragma unroll
        for (int e = 0; e < 2; e++)
            fnc[nb*2+e] = g_fn2[bb][ctile*128 + wc*64 + nb*8 + q*2 + e];
#pragma unroll
    for (int mb = 0; mb < 2; mb++) {
#pragma unroll
        for (int half = 0; half < 2; half++) {
            int row = rtile*128 + wr*32 + mb*16 + t4 + half*8;
            float bv = 3.4e38f; int bi = 0x7fffffff;
#pragma unroll
            for (int nb = 0; nb < 8; nb++) {
#pragma unroll
                for (int e = 0; e < 2; e++) {
                    float fd = fnc[nb*2+e] - 2.f * acc[mb][nb][half*2+e];
                    int col = ctile*128 + wc*64 + nb*8 + q*2 + e;
                    if (fd < bv) { bv = fd; bi = col; }
                }
            }
#pragma unroll
            for (int off = 1; off < 4; off <<= 1) {
                float ov = __shfl_xor_sync(0xffffffffu, bv, off);
                int   oi = __shfl_xor_sync(0xffffffffu, bi, off);
                if (ov < bv || (ov == bv && oi < bi)) { bv = ov; bi = oi; }
            }
            if (q == 0) {
                g_pmv[p][row][ctile*2 + wc] = bv;
                g_pmi[p][row][ctile*2 + wc] = bi;
            }
        }
    }
}

// ---------------- kernel 4: fused tail (corr reduce + mask + power + MLP) ----------------
__global__ void __launch_bounds__(512)
k_tail(const int* __restrict__ anc, const int* __restrict__ pos,
       const int* __restrict__ neg,
       const float* __restrict__ W1, const float* __restrict__ b1,
       const float* __restrict__ W2, const float* __restrict__ b2,
       float* __restrict__ out) {
    extern __shared__ __align__(16) unsigned char dsm[];
    unsigned (*msk)[16] = (unsigned(*)[16])dsm;              // 32 KB
    float* px   = (float*)(dsm + 32768);
    float* py   = px + K_;
    float* pz   = py + K_;
    float* pn   = pz + K_;
    float* qx   = pn + K_;
    float* qy   = qx + K_;
    float* qz   = qy + K_;
    float* qn   = qz + K_;
    float* s_sm = qn + K_;
    float* v    = s_sm + K_;
    float* w    = v + K_;
    float* u    = w + K_;
    float* red  = u + K_;

    int p = blockIdx.x;
    int tid = threadIdx.x;
    int warp = tid >> 5, lane = tid & 31;
    int t = p >> 1, n = p & 1;
    int ba = anc[t];
    int bb = n ? neg[t] : pos[t];

    // ---- stage 1: reduce argmin partials -> s, q_c ----
    {
        int k = tid;
        float bv = 3.4e38f; int bi = 0x7fffffff;
#pragma unroll
        for (int j = 0; j < 8; j++) {
            float pv = g_pmv[p][k][j];
            int   pi = g_pmi[p][k][j];
            if (pv < bv || (pv == bv && pi < bi)) { bv = pv; bi = pi; }
        }
        float fn2b = g_fn2[bb][bi];
        float dot  = 0.5f * (fn2b - bv);
        float cosv = dot / (g_fn[ba][k] * g_fn[bb][bi] + 1e-8f);
        s_sm[k] = cosv > 0.f ? cosv : 0.f;
        float x = g_cent[ba][k][0], y = g_cent[ba][k][1], z = g_cent[ba][k][2];
        px[k] = x; py[k] = y; pz[k] = z; pn[k] = x*x + y*y + z*z;
        x = g_cent[bb][bi][0]; y = g_cent[bb][bi][1]; z = g_cent[bb][bi][2];
        qx[k] = x; qy[k] = y; qz[k] = z; qn[k] = x*x + y*y + z*z;
    }
    __syncthreads();

    // ---- stage 2: geo mask via ballot, into SMEM ----
    {
        int neffa = g_neff[ba], neffb = g_neff[bb];
        for (int k = warp; k < K_; k += 16) {
            float pxk = px[k], pyk = py[k], pzk = pz[k], pnk = pn[k];
            float qxk = qx[k], qyk = qy[k], qzk = qz[k], qnk = qn[k];
            bool kv = (k < neffa);
#pragma unroll 4
            for (int ww = 0; ww < 16; ww++) {
                int l = ww * 32 + lane;
                float dp2 = fmaxf(pnk + pn[l] - 2.f*(pxk*px[l] + pyk*py[l] + pzk*pz[l]), 0.f) + 1e-12f;
                float dq2 = fmaxf(qnk + qn[l] - 2.f*(qxk*qx[l] + qyk*qy[l] + qzk*qz[l]), 0.f) + 1e-12f;
                float uu = dp2 + dq2 - 0.25f;
                bool geo = (uu < 0.f) || (4.f * dp2 * dq2 > uu * uu);
                bool ok = geo && kv && (l < neffb) && (l != k);
                unsigned word = __ballot_sync(0xffffffffu, ok);
                if (lane == 0) msk[k][ww] = word;
            }
        }
    }
    v[tid] = 0.044194173824159216f;   // 1/sqrt(512)
    __syncthreads();

    // ---- stage 3: power iteration ----
    for (int it = 0; it < 20; it++) {
        u[tid] = s_sm[tid] * v[tid];
        __syncthreads();
        float ur[16];
#pragma unroll
        for (int c = 0; c < 16; c++) ur[c] = u[c * 32 + lane];
        for (int k = warp; k < K_; k += 16) {
            const uint4* m4 = (const uint4*)msk[k];
            float acc = 0.f;
#pragma unroll
            for (int c4 = 0; c4 < 4; c4++) {
                uint4 mw = m4[c4];
                if ((mw.x >> lane) & 1u) acc += ur[c4 * 4 + 0];
                if ((mw.y >> lane) & 1u) acc += ur[c4 * 4 + 1];
                if ((mw.z >> lane) & 1u) acc += ur[c4 * 4 + 2];
                if ((mw.w >> lane) & 1u) acc += ur[c4 * 4 + 3];
            }
#pragma unroll
            for (int o = 16; o; o >>= 1) acc += __shfl_xor_sync(0xffffffffu, acc, o);
            if (lane == 0) w[k] = acc * s_sm[k];
        }
        __syncthreads();
        float x = w[tid];
        float sq = x * x;
#pragma unroll
        for (int o = 16; o; o >>= 1) sq += __shfl_xor_sync(0xffffffffu, sq, o);
        if (lane == 0) red[warp] = sq;
        __syncthreads();
        if (warp == 0) {
            float r = (lane < 16) ? red[lane] : 0.f;
#pragma unroll
            for (int o = 8; o; o >>= 1) r += __shfl_xor_sync(0xffffffffu, r, o);
            if (lane == 0) red[0] = 1.f / (sqrtf(r) + 1e-8f);
        }
        __syncthreads();
        v[tid] = x * red[0];
        __syncthreads();
    }
    // ---- sort descending ----
    for (int size = 2; size <= K_; size <<= 1) {
        for (int stride = size >> 1; stride > 0; stride >>= 1) {
            int i = tid, j = i ^ stride;
            if (j > i) {
                float vi = v[i], vj = v[j];
                bool up = ((i & size) == 0);
                bool sw = up ? (vj > vi) : (vi > vj);
                if (sw) { v[i] = vj; v[j] = vi; }
            }
            __syncthreads();
        }
    }
    // ---- MLP ----
    float hj = b1[tid];
#pragma unroll 4
    for (int k = 0; k < K_; k++)
        hj = fmaf(v[k], W1[(size_t)k * K_ + tid], hj);
    hj = hj > 0.f ? hj : 0.f;
    float contrib = hj * W2[tid];
#pragma unroll
    for (int o = 16; o; o >>= 1) contrib += __shfl_xor_sync(0xffffffffu, contrib, o);
    if (lane == 0) red[warp] = contrib;
    __syncthreads();
    if (tid == 0) {
        float sum = 0.f;
#pragma unroll
        for (int i = 0; i < 16; i++) sum += red[i];
        sum += b2[0];
        out[p]       = 1.f / (1.f + expf(-sum));
        out[NP_ + p] = (p & 1) ? 0.f : 1.f;
    }
}

extern "C" void kernel_launch(void* const* d_in, const int* in_sizes, int n_in,
                              void* d_out, int out_size) {
    const float* rt     = (const float*)d_in[0];
    const float* cents  = (const float*)d_in[1];
    const float* attn   = (const float*)d_in[2];
    const float* sas    = (const float*)d_in[3];
    const int*   num_rt = (const int*)  d_in[4];
    const int*   anc    = (const int*)  d_in[5];
    const int*   pos    = (const int*)  d_in[6];
    const int*   neg    = (const int*)  d_in[7];
    const float* W_in   = (const float*)d_in[8];
    const float* b_in   = (const float*)d_in[9];
    const float* W1     = (const float*)d_in[10];
    const float* b1     = (const float*)d_in[11];
    const float* W2     = (const float*)d_in[12];
    const float* b2     = (const float*)d_in[13];
    float* out = (float*)d_out;

    static int s_init = 0;
    if (!s_init) {
        cudaFuncSetAttribute(k_featmma, cudaFuncAttributeMaxDynamicSharedMemorySize, 98304);
        cudaFuncSetAttribute(k_gemm,    cudaFuncAttributeMaxDynamicSharedMemorySize, 98304);
        cudaFuncSetAttribute(k_tail,    cudaFuncAttributeMaxDynamicSharedMemorySize, 57472);
        s_init = 1;
    }

    k_topk   <<<B_, 512>>>(attn, num_rt, cents, sas);
    k_wt     <<<C_, C_>>>(W_in);
    k_gather <<<B_*K_/8, 256>>>(rt);
    k_featmma<<<dim3(2, 4, B_), 256, 98304>>>(b_in);
    k_fn     <<<B_*K_/256, 256>>>();
    k_gemm   <<<dim3(4, 4, NP_), 256, 98304>>>(anc, pos, neg);
    k_tail   <<<NP_, 512, 57472>>>(anc, pos, neg, W1, b1, W2, b2, out);
}

// round 8
// speedup vs baseline: 1.0591x; 1.0080x over previous
#include <cuda_runtime.h>
#include <cuda_bf16.h>
#include <math.h>
#include <stdint.h>

#define B_ 64
#define N_ 1024
#define C_ 256
#define K_ 512
#define T_ 64
#define NP_ 128   // T*2 pairs

// ---------------- static device scratch ----------------
static __device__ int      g_top_idx[B_][K_];
static __device__ int      g_neff[B_];
static __device__ float    g_cent[B_][K_][3];
static __device__ __align__(16) __nv_bfloat16 g_rh[B_][K_][C_];   // gathered rt hi
static __device__ __align__(16) __nv_bfloat16 g_rl[B_][K_][C_];   // gathered rt lo
static __device__ __align__(16) __nv_bfloat16 g_wh[C_][C_];       // W_in^T hi [n][k]
static __device__ __align__(16) __nv_bfloat16 g_wl[C_][C_];       // W_in^T lo
static __device__ __align__(16) __nv_bfloat16 g_fbh[B_][K_][C_];  // feat hi
static __device__ __align__(16) __nv_bfloat16 g_fbl[B_][K_][C_];  // feat lo
static __device__ float    g_fn2p[B_][K_][4];
static __device__ float    g_fn2[B_][K_];
static __device__ float    g_fn [B_][K_];
static __device__ float    g_pmv[NP_][K_][8];
static __device__ int      g_pmi[NP_][K_][8];

// ---------------- asm helpers ----------------
__device__ __forceinline__ uint32_t smem_u32(const void* p) {
    uint32_t a;
    asm("{ .reg .u64 t; cvta.to.shared.u64 t, %1; cvt.u32.u64 %0, t; }" : "=r"(a) : "l"(p));
    return a;
}
__device__ __forceinline__ void ldsm4(uint32_t* r, uint32_t a) {
    asm volatile("ldmatrix.sync.aligned.m8n8.x4.shared.b16 {%0,%1,%2,%3}, [%4];"
        : "=r"(r[0]), "=r"(r[1]), "=r"(r[2]), "=r"(r[3]) : "r"(a));
}
__device__ __forceinline__ void mma16816(float* c, const uint32_t* a, uint32_t b0, uint32_t b1) {
    asm volatile("mma.sync.aligned.m16n8k16.row.col.f32.bf16.bf16.f32 "
        "{%0,%1,%2,%3}, {%4,%5,%6,%7}, {%8,%9}, {%0,%1,%2,%3};"
        : "+f"(c[0]), "+f"(c[1]), "+f"(c[2]), "+f"(c[3])
        : "r"(a[0]), "r"(a[1]), "r"(a[2]), "r"(a[3]), "r"(b0), "r"(b1));
}
#define CP_ASYNC16(dst, src) asm volatile("cp.async.cg.shared.global [%0], [%1], 16;" :: "r"(dst), "l"(src))
#define CP_COMMIT()          asm volatile("cp.async.commit_group;" ::: "memory")
#define CP_WAIT0()           asm volatile("cp.async.wait_group 0;" ::: "memory")
#define CP_WAIT1()           asm volatile("cp.async.wait_group 1;" ::: "memory")

// SW64 swizzle for 64B-wide rows (conflict-free 8-row ldmatrix)
#define SWZ64(off) ((off) ^ (((off) >> 3) & 0x30))

__device__ __forceinline__ uint32_t split_pack_hi(float v0, float v1, uint32_t& lo) {
    __nv_bfloat16 h0 = __float2bfloat16_rn(v0);
    __nv_bfloat16 h1 = __float2bfloat16_rn(v1);
    __nv_bfloat16 l0 = __float2bfloat16_rn(v0 - __bfloat162float(h0));
    __nv_bfloat16 l1 = __float2bfloat16_rn(v1 - __bfloat162float(h1));
    lo = (uint32_t)__bfloat16_as_ushort(l0) | ((uint32_t)__bfloat16_as_ushort(l1) << 16);
    return (uint32_t)__bfloat16_as_ushort(h0) | ((uint32_t)__bfloat16_as_ushort(h1) << 16);
}

// ---------------- kernel 1: masked top-K via bitonic sort ----------------
__global__ void k_topk(const float* __restrict__ attn,
                       const int*   __restrict__ num_rt,
                       const float* __restrict__ cents,
                       const float* __restrict__ sas) {
    int b = blockIdx.x;
    __shared__ float sv[N_];
    __shared__ int   si[N_];
    int nr = num_rt[b];
    for (int i = threadIdx.x; i < N_; i += blockDim.x) {
        sv[i] = (i < nr) ? attn[b * N_ + i] : -1e9f;
        si[i] = i;
    }
    for (int size = 2; size <= N_; size <<= 1) {
        for (int stride = size >> 1; stride > 0; stride >>= 1) {
            __syncthreads();
            for (int i = threadIdx.x; i < N_; i += blockDim.x) {
                int j = i ^ stride;
                if (j > i) {
                    float vi = sv[i], vj = sv[j];
                    int   ii = si[i], ij = si[j];
                    bool up = ((i & size) == 0);
                    bool jFirst = (vj > vi) || (vj == vi && ij < ii);
                    bool iFirst = (vi > vj) || (vi == vj && ii < ij);
                    bool sw = up ? jFirst : iFirst;
                    if (sw) { sv[i] = vj; sv[j] = vi; si[i] = ij; si[j] = ii; }
                }
            }
        }
    }
    __syncthreads();
    float sh0 = sas[b*4+0], sh1 = sas[b*4+1], sh2 = sas[b*4+2], sc = sas[b*4+3];
    for (int k = threadIdx.x; k < K_; k += blockDim.x) {
        int id = si[k];
        g_top_idx[b][k] = id;
        const float* cp = cents + ((size_t)b * N_ + id) * 3;
        float x = cp[0], y = cp[1], z = cp[2];
        if (id < nr) { x = fmaf(x, sc, sh0); y = fmaf(y, sc, sh1); z = fmaf(z, sc, sh2); }
        g_cent[b][k][0] = x; g_cent[b][k][1] = y; g_cent[b][k][2] = z;
    }
    if (threadIdx.x == 0) g_neff[b] = nr < K_ ? nr : K_;
}

// ---------------- prep: W_in^T bf16 hi/lo ----------------
__global__ void k_wt(const float* __restrict__ W_in) {
    int k = blockIdx.x, n = threadIdx.x;
    float v = W_in[k * C_ + n];
    __nv_bfloat16 h = __float2bfloat16_rn(v);
    __nv_bfloat16 l = __float2bfloat16_rn(v - __bfloat162float(h));
    g_wh[n][k] = h;
    g_wl[n][k] = l;
}

// ---------------- prep: gather top-K rt rows to bf16 hi/lo ----------------
__global__ void k_gather(const float* __restrict__ rt) {
    int idx  = blockIdx.x * 8 + (threadIdx.x >> 5);
    int lane = threadIdx.x & 31;
    int b = idx >> 9, k = idx & (K_ - 1);
    int src = g_top_idx[b][k];
    const float4* r = (const float4*)(rt + ((size_t)b * N_ + src) * C_);
    float4 u = r[lane * 2], w2 = r[lane * 2 + 1];
    float f[8] = {u.x, u.y, u.z, u.w, w2.x, w2.y, w2.z, w2.w};
    uint32_t hw[4], lw[4];
#pragma unroll
    for (int q = 0; q < 4; q++) hw[q] = split_pack_hi(f[q*2], f[q*2+1], lw[q]);
    *(uint4*)&g_rh[b][k][lane * 8] = make_uint4(hw[0], hw[1], hw[2], hw[3]);
    *(uint4*)&g_rl[b][k][lane * 8] = make_uint4(lw[0], lw[1], lw[2], lw[3]);
}

// ---------------- GEMM plumbing: 128x128 tile, K-chunk 32 (SW64), 3 stages ----------------
// Stage = 4 tiles (Ah,Al,Bh,Bl) x 128 rows x 64B = 32 KB. 3 stages = 96 KB -> 2 CTAs/SM.
__device__ __forceinline__ void gem_prefetch(const uint4* const* gsrc, uint32_t sb,
                                             int tid, int kc, int stage) {
    uint32_t dbase = sb + stage * 32768;
#pragma unroll
    for (int tl = 0; tl < 4; tl++) {
        const uint4* s = gsrc[tl];
#pragma unroll
        for (int i = 0; i < 2; i++) {
            int idx = tid + i * 256;
            int rr = idx >> 2, uu = idx & 3;
            uint32_t off = (uint32_t)((rr << 6) + (uu << 4));
            CP_ASYNC16(dbase + tl * 8192 + SWZ64(off), s + rr * 32 + kc * 4 + uu);
        }
    }
    CP_COMMIT();
}

// mainloop: 8 K-chunks of 32; 8 warps, each owns 64x64 output; acc[2][8][4]
// Software-pipelined: B-fragment double-buffer + term-major MMA order
// (per-accumulator accumulation order identical to previous rounds).
__device__ __forceinline__ void gem_mainloop(const uint4* const* gsrc, uint32_t sb,
                                             int tid, float acc[2][8][4]) {
    int lane = tid & 31, wid = tid >> 5;
    int wr = wid >> 1, wc = wid & 1;
    int mat = lane >> 3, rlo = lane & 7;
    // fragment rows; swizzle XOR depends only on rlo bits 1-2 (constant)
    uint32_t xr   = (uint32_t)((rlo & 6) << 3);
    int rowA0 = wr * 32 + rlo + ((mat & 1) << 3);      // mb=0
    int rowB0 = wc * 64 + rlo + ((mat & 1) << 3);      // nbp=0
    uint32_t baseA0 = (uint32_t)(rowA0 * 64);
    uint32_t baseA1 = baseA0 + 16 * 64;
    uint32_t baseB  = (uint32_t)(rowB0 * 64);
    uint32_t kqsel  = (uint32_t)((mat >> 1) * 16);

    gem_prefetch(gsrc, sb, tid, 0, 0);
    gem_prefetch(gsrc, sb, tid, 1, 1);
    for (int kc = 0; kc < 8; kc++) {
        if (kc < 7) { CP_WAIT1(); } else { CP_WAIT0(); }
        __syncthreads();
        if (kc < 6) {
            int nkc = kc + 2;
            gem_prefetch(gsrc, sb, tid, nkc, nkc - (nkc / 3) * 3);
        }
        uint32_t tb = sb + (kc - (kc / 3) * 3) * 32768;
#pragma unroll
        for (int ks = 0; ks < 2; ks++) {
            uint32_t kq = (uint32_t)(ks * 32) + kqsel;   // (2*ks + (mat>>1)) * 16
            uint32_t kqx = kq ^ xr;
            // A fragments for both row-halves (hi at +0, lo at +8192)
            uint32_t af[2][2][4];
            {
                uint32_t ad0 = tb + baseA0 + kqx;
                ldsm4(af[0][0], ad0); ldsm4(af[0][1], ad0 + 8192);
                uint32_t ad1 = tb + baseA1 + kqx;
                ldsm4(af[1][0], ad1); ldsm4(af[1][1], ad1 + 8192);
            }
            // B fragment double buffer (hi at +16384, lo at +24576)
            uint32_t bh[2][4], bl[2][4];
            {
                uint32_t ab = tb + 16384 + baseB + kqx;
                ldsm4(bh[0], ab); ldsm4(bl[0], ab + 8192);
            }
#pragma unroll
            for (int nbp = 0; nbp < 4; nbp++) {
                int cur = nbp & 1, nxt = cur ^ 1;
                if (nbp < 3) {
                    uint32_t ab = tb + 16384 + baseB + (uint32_t)((nbp + 1) * 16 * 64) + kqx;
                    ldsm4(bh[nxt], ab); ldsm4(bl[nxt], ab + 8192);
                }
                // term hh on all 4 accumulators (reuse distance 4)
                mma16816(acc[0][nbp*2],   af[0][0], bh[cur][0], bh[cur][2]);
                mma16816(acc[0][nbp*2+1], af[0][0], bh[cur][1], bh[cur][3]);
                mma16816(acc[1][nbp*2],   af[1][0], bh[cur][0], bh[cur][2]);
                mma16816(acc[1][nbp*2+1], af[1][0], bh[cur][1], bh[cur][3]);
                // term hl
                mma16816(acc[0][nbp*2],   af[0][0], bl[cur][0], bl[cur][2]);
                mma16816(acc[0][nbp*2+1], af[0][0], bl[cur][1], bl[cur][3]);
                mma16816(acc[1][nbp*2],   af[1][0], bl[cur][0], bl[cur][2]);
                mma16816(acc[1][nbp*2+1], af[1][0], bl[cur][1], bl[cur][3]);
                // term lh
                mma16816(acc[0][nbp*2],   af[0][1], bh[cur][0], bh[cur][2]);
                mma16816(acc[0][nbp*2+1], af[0][1], bh[cur][1], bh[cur][3]);
                mma16816(acc[1][nbp*2],   af[1][1], bh[cur][0], bh[cur][2]);
                mma16816(acc[1][nbp*2+1], af[1][1], bh[cur][1], bh[cur][3]);
            }
        }
    }
    __syncthreads();
}

// ---------------- kernel 2: feat = gather(rt) @ W_in + b_in via MMA ----------------
__global__ void __launch_bounds__(256, 2)
k_featmma(const float* __restrict__ b_in) {
    extern __shared__ __align__(128) unsigned char dsm[];
    int b     = blockIdx.z;
    int rtile = blockIdx.y;
    int ctile = blockIdx.x;          // n half: 0 or 1
    int tid = threadIdx.x, lane = tid & 31, wid = tid >> 5;
    int wr = wid >> 1, wc = wid & 1;
    uint32_t sb = smem_u32(dsm);

    const uint4* gsrc[4];
    gsrc[0] = (const uint4*)&g_rh[b][rtile * 128][0];
    gsrc[1] = (const uint4*)&g_rl[b][rtile * 128][0];
    gsrc[2] = (const uint4*)&g_wh[ctile * 128][0];
    gsrc[3] = (const uint4*)&g_wl[ctile * 128][0];

    float acc[2][8][4];
#pragma unroll
    for (int mb = 0; mb < 2; mb++)
#pragma unroll
        for (int nb = 0; nb < 8; nb++)
#pragma unroll
            for (int c = 0; c < 4; c++) acc[mb][nb][c] = 0.f;

    gem_mainloop(gsrc, sb, tid, acc);

    int t4 = lane >> 2, q = lane & 3;
#pragma unroll
    for (int mb = 0; mb < 2; mb++) {
#pragma unroll
        for (int half = 0; half < 2; half++) {
            int row = rtile * 128 + wr * 32 + mb * 16 + t4 + half * 8;
            float s8 = 0.f;
#pragma unroll
            for (int nb = 0; nb < 8; nb++) {
                int col = ctile * 128 + wc * 64 + nb * 8 + q * 2;
                float f0 = acc[mb][nb][half*2+0] + b_in[col];
                float f1 = acc[mb][nb][half*2+1] + b_in[col + 1];
                uint32_t lw;
                uint32_t hw = split_pack_hi(f0, f1, lw);
                *(uint32_t*)&g_fbh[b][row][col] = hw;
                *(uint32_t*)&g_fbl[b][row][col] = lw;
                s8 += f0 * f0 + f1 * f1;
            }
            s8 += __shfl_xor_sync(0xffffffffu, s8, 1);
            s8 += __shfl_xor_sync(0xffffffffu, s8, 2);
            if (q == 0) g_fn2p[b][row][ctile * 2 + wc] = s8;
        }
    }
}

// ---------------- kernel 2b: finalize norms ----------------
__global__ void k_fn() {
    int i = blockIdx.x * 256 + threadIdx.x;
    const float* pp = &g_fn2p[0][0][0] + (size_t)i * 4;
    float s = (pp[0] + pp[1]) + (pp[2] + pp[3]);
    (&g_fn2[0][0])[i] = s;
    (&g_fn [0][0])[i] = sqrtf(s);
}

// ---------------- kernel 3: G tile + fused partial argmin ----------------
__global__ void __launch_bounds__(256, 2)
k_gemm(const int* __restrict__ anc,
       const int* __restrict__ pos,
       const int* __restrict__ neg) {
    extern __shared__ __align__(128) unsigned char dsm[];
    int p = blockIdx.z;
    int t = p >> 1, nn = p & 1;
    int ba = anc[t];
    int bb = nn ? neg[t] : pos[t];
    int rtile = blockIdx.y, ctile = blockIdx.x;
    int tid = threadIdx.x, lane = tid & 31, wid = tid >> 5;
    int wr = wid >> 1, wc = wid & 1;
    uint32_t sb = smem_u32(dsm);

    const uint4* gsrc[4];
    gsrc[0] = (const uint4*)&g_fbh[ba][rtile * 128][0];
    gsrc[1] = (const uint4*)&g_fbl[ba][rtile * 128][0];
    gsrc[2] = (const uint4*)&g_fbh[bb][ctile * 128][0];
    gsrc[3] = (const uint4*)&g_fbl[bb][ctile * 128][0];

    float acc[2][8][4];
#pragma unroll
    for (int mb = 0; mb < 2; mb++)
#pragma unroll
        for (int nb = 0; nb < 8; nb++)
#pragma unroll
            for (int c = 0; c < 4; c++) acc[mb][nb][c] = 0.f;

    gem_mainloop(gsrc, sb, tid, acc);

    int t4 = lane >> 2, q = lane & 3;
    float fnc[16];
#pragma unroll
    for (int nb = 0; nb < 8; nb++)
#pragma unroll
        for (int e = 0; e < 2; e++)
            fnc[nb*2+e] = g_fn2[bb][ctile*128 + wc*64 + nb*8 + q*2 + e];
#pragma unroll
    for (int mb = 0; mb < 2; mb++) {
#pragma unroll
        for (int half = 0; half < 2; half++) {
            int row = rtile*128 + wr*32 + mb*16 + t4 + half*8;
            float bv = 3.4e38f; int bi = 0x7fffffff;
#pragma unroll
            for (int nb = 0; nb < 8; nb++) {
#pragma unroll
                for (int e = 0; e < 2; e++) {
                    float fd = fnc[nb*2+e] - 2.f * acc[mb][nb][half*2+e];
                    int col = ctile*128 + wc*64 + nb*8 + q*2 + e;
                    if (fd < bv) { bv = fd; bi = col; }
                }
            }
#pragma unroll
            for (int off = 1; off < 4; off <<= 1) {
                float ov = __shfl_xor_sync(0xffffffffu, bv, off);
                int   oi = __shfl_xor_sync(0xffffffffu, bi, off);
                if (ov < bv || (ov == bv && oi < bi)) { bv = ov; bi = oi; }
            }
            if (q == 0) {
                g_pmv[p][row][ctile*2 + wc] = bv;
                g_pmi[p][row][ctile*2 + wc] = bi;
            }
        }
    }
}

// ---------------- kernel 4: fused tail (corr reduce + mask + power + MLP) ----------------
__global__ void __launch_bounds__(512)
k_tail(const int* __restrict__ anc, const int* __restrict__ pos,
       const int* __restrict__ neg,
       const float* __restrict__ W1, const float* __restrict__ b1,
       const float* __restrict__ W2, const float* __restrict__ b2,
       float* __restrict__ out) {
    extern __shared__ __align__(16) unsigned char dsm[];
    unsigned (*msk)[16] = (unsigned(*)[16])dsm;              // 32 KB
    float* px   = (float*)(dsm + 32768);
    float* py   = px + K_;
    float* pz   = py + K_;
    float* pn   = pz + K_;
    float* qx   = pn + K_;
    float* qy   = qx + K_;
    float* qz   = qy + K_;
    float* qn   = qz + K_;
    float* s_sm = qn + K_;
    float* v    = s_sm + K_;
    float* w    = v + K_;
    float* u    = w + K_;
    float* red  = u + K_;

    int p = blockIdx.x;
    int tid = threadIdx.x;
    int warp = tid >> 5, lane = tid & 31;
    int t = p >> 1, n = p & 1;
    int ba = anc[t];
    int bb = n ? neg[t] : pos[t];

    // ---- stage 1: reduce argmin partials -> s, q_c ----
    {
        int k = tid;
        float bv = 3.4e38f; int bi = 0x7fffffff;
#pragma unroll
        for (int j = 0; j < 8; j++) {
            float pv = g_pmv[p][k][j];
            int   pi = g_pmi[p][k][j];
            if (pv < bv || (pv == bv && pi < bi)) { bv = pv; bi = pi; }
        }
        float fn2b = g_fn2[bb][bi];
        float dot  = 0.5f * (fn2b - bv);
        float cosv = dot / (g_fn[ba][k] * g_fn[bb][bi] + 1e-8f);
        s_sm[k] = cosv > 0.f ? cosv : 0.f;
        float x = g_cent[ba][k][0], y = g_cent[ba][k][1], z = g_cent[ba][k][2];
        px[k] = x; py[k] = y; pz[k] = z; pn[k] = x*x + y*y + z*z;
        x = g_cent[bb][bi][0]; y = g_cent[bb][bi][1]; z = g_cent[bb][bi][2];
        qx[k] = x; qy[k] = y; qz[k] = z; qn[k] = x*x + y*y + z*z;
    }
    __syncthreads();

    // ---- stage 2: geo mask via ballot, into SMEM ----
    {
        int neffa = g_neff[ba], neffb = g_neff[bb];
        for (int k = warp; k < K_; k += 16) {
            float pxk = px[k], pyk = py[k], pzk = pz[k], pnk = pn[k];
            float qxk = qx[k], qyk = qy[k], qzk = qz[k], qnk = qn[k];
            bool kv = (k < neffa);
#pragma unroll 4
            for (int ww = 0; ww < 16; ww++) {
                int l = ww * 32 + lane;
                float dp2 = fmaxf(pnk + pn[l] - 2.f*(pxk*px[l] + pyk*py[l] + pzk*pz[l]), 0.f) + 1e-12f;
                float dq2 = fmaxf(qnk + qn[l] - 2.f*(qxk*qx[l] + qyk*qy[l] + qzk*qz[l]), 0.f) + 1e-12f;
                float uu = dp2 + dq2 - 0.25f;
                bool geo = (uu < 0.f) || (4.f * dp2 * dq2 > uu * uu);
                bool ok = geo && kv && (l < neffb) && (l != k);
                unsigned word = __ballot_sync(0xffffffffu, ok);
                if (lane == 0) msk[k][ww] = word;
            }
        }
    }
    v[tid] = 0.044194173824159216f;   // 1/sqrt(512)
    __syncthreads();

    // ---- stage 3: power iteration ----
    for (int it = 0; it < 20; it++) {
        u[tid] = s_sm[tid] * v[tid];
        __syncthreads();
        float ur[16];
#pragma unroll
        for (int c = 0; c < 16; c++) ur[c] = u[c * 32 + lane];
        for (int k = warp; k < K_; k += 16) {
            const uint4* m4 = (const uint4*)msk[k];
            float acc = 0.f;
#pragma unroll
            for (int c4 = 0; c4 < 4; c4++) {
                uint4 mw = m4[c4];
                if ((mw.x >> lane) & 1u) acc += ur[c4 * 4 + 0];
                if ((mw.y >> lane) & 1u) acc += ur[c4 * 4 + 1];
                if ((mw.z >> lane) & 1u) acc += ur[c4 * 4 + 2];
                if ((mw.w >> lane) & 1u) acc += ur[c4 * 4 + 3];
            }
#pragma unroll
            for (int o = 16; o; o >>= 1) acc += __shfl_xor_sync(0xffffffffu, acc, o);
            if (lane == 0) w[k] = acc * s_sm[k];
        }
        __syncthreads();
        float x = w[tid];
        float sq = x * x;
#pragma unroll
        for (int o = 16; o; o >>= 1) sq += __shfl_xor_sync(0xffffffffu, sq, o);
        if (lane == 0) red[warp] = sq;
        __syncthreads();
        if (warp == 0) {
            float r = (lane < 16) ? red[lane] : 0.f;
#pragma unroll
            for (int o = 8; o; o >>= 1) r += __shfl_xor_sync(0xffffffffu, r, o);
            if (lane == 0) red[0] = 1.f / (sqrtf(r) + 1e-8f);
        }
        __syncthreads();
        v[tid] = x * red[0];
        __syncthreads();
    }
    // ---- sort descending ----
    for (int size = 2; size <= K_; size <<= 1) {
        for (int stride = size >> 1; stride > 0; stride >>= 1) {
            int i = tid, j = i ^ stride;
            if (j > i) {
                float vi = v[i], vj = v[j];
                bool up = ((i & size) == 0);
                bool sw = up ? (vj > vi) : (vi > vj);
                if (sw) { v[i] = vj; v[j] = vi; }
            }
            __syncthreads();
        }
    }
    // ---- MLP ----
    float hj = b1[tid];
#pragma unroll 4
    for (int k = 0; k < K_; k++)
        hj = fmaf(v[k], W1[(size_t)k * K_ + tid], hj);
    hj = hj > 0.f ? hj : 0.f;
    float contrib = hj * W2[tid];
#pragma unroll
    for (int o = 16; o; o >>= 1) contrib += __shfl_xor_sync(0xffffffffu, contrib, o);
    if (lane == 0) red[warp] = contrib;
    __syncthreads();
    if (tid == 0) {
        float sum = 0.f;
#pragma unroll
        for (int i = 0; i < 16; i++) sum += red[i];
        sum += b2[0];
        out[p]       = 1.f / (1.f + expf(-sum));
        out[NP_ + p] = (p & 1) ? 0.f : 1.f;
    }
}

extern "C" void kernel_launch(void* const* d_in, const int* in_sizes, int n_in,
                              void* d_out, int out_size) {
    const float* rt     = (const float*)d_in[0];
    const float* cents  = (const float*)d_in[1];
    const float* attn   = (const float*)d_in[2];
    const float* sas    = (const float*)d_in[3];
    const int*   num_rt = (const int*)  d_in[4];
    const int*   anc    = (const int*)  d_in[5];
    const int*   pos    = (const int*)  d_in[6];
    const int*   neg    = (const int*)  d_in[7];
    const float* W_in   = (const float*)d_in[8];
    const float* b_in   = (const float*)d_in[9];
    const float* W1     = (const float*)d_in[10];
    const float* b1     = (const float*)d_in[11];
    const float* W2     = (const float*)d_in[12];
    const float* b2     = (const float*)d_in[13];
    float* out = (float*)d_out;

    static int s_init = 0;
    if (!s_init) {
        cudaFuncSetAttribute(k_featmma, cudaFuncAttributeMaxDynamicSharedMemorySize, 98304);
        cudaFuncSetAttribute(k_gemm,    cudaFuncAttributeMaxDynamicSharedMemorySize, 98304);
        cudaFuncSetAttribute(k_tail,    cudaFuncAttributeMaxDynamicSharedMemorySize, 57472);
        s_init = 1;
    }

    k_topk   <<<B_, 512>>>(attn, num_rt, cents, sas);
    k_wt     <<<C_, C_>>>(W_in);
    k_gather <<<B_*K_/8, 256>>>(rt);
    k_featmma<<<dim3(2, 4, B_), 256, 98304>>>(b_in);
    k_fn     <<<B_*K_/256, 256>>>();
    k_gemm   <<<dim3(4, 4, NP_), 256, 98304>>>(anc, pos, neg);
    k_tail   <<<NP_, 512, 57472>>>(anc, pos, neg, W1, b1, W2, b2, out);
}